// round 14
// baseline (speedup 1.0000x reference)
#include <cuda_runtime.h>
#include <math.h>

// Equilibrium propagation, 256 serial iterations (R12 = R11 pipeline @ G=32).
//
//  - 32 persistent CTAs x 256 threads; CTA c owns 128 output columns.
//  - Pipeline (publish(it+1) depends only on gather(it-1)):
//      Phase A: h-threads (0..127) gather(it) sweep of 32 tagged words
//               ||  o-threads (128..255) pass1(it) + o Adam
//      Phase B: all 256 threads pass2(it+1) split (64 MACs each) ->
//               h publishes tagged partial(it+1) -> hAdam(it).
//  - Tagged 8B words {it, f32} via st/ld.relaxed.gpu (single-copy atomic,
//    self-validating). 4-deep buffers (it & 3): publish of it+1 overwrites
//    it-3, and all gathers(it-3) provably completed (publish(it+1) requires
//    gather(it) done requires all published it requires ... chain).
//  - Redundant h Adam in every CTA (fixed-order sums -> bitwise identical).
//  - W2 slice in smem twice: W2c [128 cols][132] (pass1, col-major) and
//    W2r [128 rows][132] (pass2, row-major) -> conflict-free LDS.128.

#define G      32
#define T      256
#define HID    128
#define OUT    4096
#define COLS   128            // OUT / G
#define IN     65536
#define XCTAS  256
#define XROWS  (IN / XCTAS)   // 256
#define PITCH  132            // 528 B pitch: float4-aligned, conflict-free

__device__ float g_xpart[XCTAS * HID];
__device__ unsigned long long g_part[4][G][HID];   // [it&3][cta][row] {tag,val}

__device__ __forceinline__ unsigned long long ldx(const unsigned long long* p) {
    unsigned long long v;
    asm volatile("ld.relaxed.gpu.global.b64 %0, [%1];" : "=l"(v) : "l"(p));
    return v;
}
__device__ __forceinline__ void stx(unsigned long long* p, unsigned long long v) {
    asm volatile("st.relaxed.gpu.global.b64 [%0], %1;" :: "l"(p), "l"(v) : "memory");
}
__device__ __forceinline__ float clampf(float v) {
    return fminf(fmaxf(v, 0.f), 1.f);
}
__device__ __forceinline__ unsigned long long pack(int tag, float v) {
    return ((unsigned long long)(unsigned)tag << 32) |
           (unsigned long long)__float_as_uint(v);
}

// ---------------------------------------------------------------------------
// Kernel A: xW1 partials (one-time, HBM-bound) + tag reset of all 4 depths
// (replay safety: stale tags from a prior graph replay must not match).
// ---------------------------------------------------------------------------
__global__ __launch_bounds__(256) void xw1_kernel(
    const float* __restrict__ x, const float* __restrict__ W1)
{
    __shared__ float tmp[HID];
    int t   = threadIdx.x;
    int col = t & (HID - 1);
    int rp  = t >> 7;
    int base = blockIdx.x * XROWS + rp * (XROWS / 2);

    float acc = 0.f;
#pragma unroll 4
    for (int k = 0; k < XROWS / 2; ++k) {
        int i = base + k;
        acc += clampf(x[i]) * W1[(size_t)i * HID + col];
    }
    if (rp == 1) tmp[col] = acc;
    __syncthreads();
    if (rp == 0) g_xpart[blockIdx.x * HID + col] = acc + tmp[col];

    int gid = blockIdx.x * 256 + t;            // 65536 threads; 16384 words
    if (gid < 4 * G * HID)
        ((unsigned long long*)g_part)[gid] = 0ull;
}

// ---------------------------------------------------------------------------
// Kernel B: persistent pipelined iteration kernel.
// ---------------------------------------------------------------------------
extern __shared__ float smem_dyn[];

__global__ __launch_bounds__(T, 1) void eqprop_kernel(
    const float* __restrict__ W2,
    const float* __restrict__ b_h,
    const float* __restrict__ b_out,
    const float* __restrict__ h0,
    const float* __restrict__ o0,
    const int*   __restrict__ n_it_p,
    const float* __restrict__ eps_p,
    float*       __restrict__ out)
{
    float* W2c = smem_dyn;                     // [COLS][PITCH] col-major
    float* W2r = smem_dyn + COLS * PITCH;      // [HID][PITCH]  row-major
    __shared__ __align__(16) float s_rh[HID];  // r_h(it-1) for pass1(it)
    __shared__ __align__(16) float s_ro[COLS]; // r_o(it)   for pass2(it+1)
    __shared__ __align__(16) float s_p2[HID];  // pass2 upper halves

    const int t = threadIdx.x;
    const int c = blockIdx.x;

    int n_it = *n_it_p;
    if (!(n_it > 0 && n_it < (1 << 20))) {
        n_it = (int)__int_as_float(n_it);
        if (!(n_it > 0 && n_it < (1 << 20))) n_it = 256;
    }
    const float eps = *eps_p;

    // --- W2 slice -> both smem layouts (one-time, coalesced LDG) ---
    for (int idx = t; idx < HID * COLS; idx += T) {
        int i = idx >> 7;            // hidden row  (0..127)
        int j = idx & (COLS - 1);    // local col   (0..127)
        float w = W2[(size_t)i * OUT + (size_t)c * COLS + j];
        W2c[j * PITCH + i] = w;
        W2r[i * PITCH + j] = w;
    }

    // --- per-thread state ---
    float hreg = 0.f, mh = 0.f, vh = 0.f, bh = 0.f, hW = 0.f;
    float oreg = 0.f, mo = 0.f, vo = 0.f, bo = 0.f;
    if (t < HID) {
        // fixed-order xW1[t] reduction: identical in every CTA -> identical h
        float s0 = 0.f, s1 = 0.f, s2 = 0.f, s3 = 0.f;
#pragma unroll 8
        for (int k = 0; k < XCTAS; k += 4) {
            s0 += g_xpart[(k    ) * HID + t];
            s1 += g_xpart[(k + 1) * HID + t];
            s2 += g_xpart[(k + 2) * HID + t];
            s3 += g_xpart[(k + 3) * HID + t];
        }
        hW   = (s0 + s1) + (s2 + s3);
        hreg = h0[t];
        bh   = b_h[t];
        s_rh[t] = clampf(hreg);
    } else {
        int j = t - HID;
        oreg = o0[c * COLS + j];
        bo   = b_out[c * COLS + j];
        s_ro[j] = clampf(oreg);
    }
    __syncthreads();   // W2 smem + s_rh(0) + s_ro(0) ready

    // --- prologue: publish partial(1) = W2 @ r_o(0), tag = 1 ---
    {
        const int r    = t & (HID - 1);
        const int half = t >> 7;
        const float4* wr  = (const float4*)(W2r + r * PITCH + half * 64);
        const float4* ro4 = (const float4*)(s_ro + half * 64);
        float4 a = make_float4(0.f, 0.f, 0.f, 0.f);
#pragma unroll
        for (int q = 0; q < 16; ++q) {
            float4 w = wr[q], rr = ro4[q];
            a.x += w.x * rr.x; a.y += w.y * rr.y;
            a.z += w.z * rr.z; a.w += w.w * rr.w;
        }
        float phalf = (a.x + a.y) + (a.z + a.w);
        if (half == 1) s_p2[r] = phalf;
        __syncthreads();
        if (t < HID)
            stx(&g_part[1][c][t], pack(1, phalf + s_p2[t]));
        __syncthreads();
    }

    float pw1 = 1.f, pw2 = 1.f;

    for (int it = 1; it <= n_it; ++it) {
        pw1 *= 0.9f;
        pw2 *= 0.999f;
        const float ic1 = 1.f / (1.f - pw1);
        const float ic2 = 1.f / (1.f - pw2);

        float S = 0.f;   // h-side gather result

        // ==== phase A: gather(it) [h]  ||  pass1(it) + o Adam [o] ====
        if (t < HID) {
            const unsigned long long* gb = &g_part[it & 3][0][t];
            for (;;) {
                bool ok = true;
                float a0 = 0.f, a1 = 0.f, a2 = 0.f, a3 = 0.f;
#pragma unroll
                for (int k = 0; k < G; k += 4) {
                    unsigned long long v0 = ldx(gb + (k + 0) * HID);
                    unsigned long long v1 = ldx(gb + (k + 1) * HID);
                    unsigned long long v2 = ldx(gb + (k + 2) * HID);
                    unsigned long long v3 = ldx(gb + (k + 3) * HID);
                    ok &= ((int)(v0 >> 32) == it) & ((int)(v1 >> 32) == it) &
                          ((int)(v2 >> 32) == it) & ((int)(v3 >> 32) == it);
                    a0 += __uint_as_float((unsigned)v0);
                    a1 += __uint_as_float((unsigned)v1);
                    a2 += __uint_as_float((unsigned)v2);
                    a3 += __uint_as_float((unsigned)v3);
                }
                if (ok) { S = (a0 + a1) + (a2 + a3); break; }
            }
        } else {
            const int j = t - HID;
            const float4* wc  = (const float4*)(W2c + j * PITCH);
            const float4* rh4 = (const float4*)s_rh;
            float4 a = make_float4(0.f, 0.f, 0.f, 0.f);
#pragma unroll
            for (int q = 0; q < HID / 4; ++q) {
                float4 w = wc[q], rr = rh4[q];
                a.x += w.x * rr.x; a.y += w.y * rr.y;
                a.z += w.z * rr.z; a.w += w.w * rr.w;
            }
            float y = (a.x + a.y) + (a.z + a.w);

            float ro   = clampf(oreg);
            float mask = (oreg >= 0.f && oreg <= 1.f) ? 1.f : 0.f;
            float g    = mask * (ro - bo - y);
            mo = 0.9f  * mo + 0.1f  * g;
            vo = 0.999f * vo + 0.001f * g * g;
            oreg -= eps * (mo * ic1) / (sqrtf(vo * ic2) + 1e-8f);
            s_ro[j] = clampf(oreg);               // r_o(it) for pass2(it+1)
        }
        __syncthreads();   // s_ro(it) ready; gathers complete

        // ==== phase B: pass2(it+1) split -> publish(it+1) -> hAdam(it) ====
        {
            const int r    = t & (HID - 1);
            const int half = t >> 7;
            const float4* wr  = (const float4*)(W2r + r * PITCH + half * 64);
            const float4* ro4 = (const float4*)(s_ro + half * 64);
            float4 a = make_float4(0.f, 0.f, 0.f, 0.f);
#pragma unroll
            for (int q = 0; q < 16; ++q) {
                float4 w = wr[q], rr = ro4[q];
                a.x += w.x * rr.x; a.y += w.y * rr.y;
                a.z += w.z * rr.z; a.w += w.w * rr.w;
            }
            float phalf = (a.x + a.y) + (a.z + a.w);
            if (half == 1) s_p2[r] = phalf;
            __syncthreads();

            if (t < HID) {
                stx(&g_part[(it + 1) & 3][c][t],
                    pack(it + 1, phalf + s_p2[t]));   // publish early

                // redundant h Adam(it) (bitwise identical in all CTAs)
                float rh   = clampf(hreg);
                float mask = (hreg >= 0.f && hreg <= 1.f) ? 1.f : 0.f;
                float g    = mask * (rh - bh - hW - S);
                mh = 0.9f  * mh + 0.1f  * g;
                vh = 0.999f * vh + 0.001f * g * g;
                hreg -= eps * (mh * ic1) / (sqrtf(vh * ic2) + 1e-8f);
                s_rh[t] = clampf(hreg);               // r_h(it) for pass1(it+1)
            }
        }
        __syncthreads();   // s_rh(it) published to o-side
    }

    if (t >= HID)
        out[c * COLS + (t - HID)] = oreg;
}

// ---------------------------------------------------------------------------
extern "C" void kernel_launch(void* const* d_in, const int* in_sizes, int n_in,
                              void* d_out, int out_size)
{
    const float* x     = (const float*)d_in[0];
    const float* W1    = (const float*)d_in[1];
    const float* W2    = (const float*)d_in[2];
    // d_in[3] = b_in (unused by the reference math)
    const float* b_h   = (const float*)d_in[4];
    const float* b_out = (const float*)d_in[5];
    const float* h0    = (const float*)d_in[6];
    const float* o0    = (const float*)d_in[7];
    const int*   n_it  = (const int*)d_in[8];
    const float* eps   = (const float*)d_in[9];
    float* out = (float*)d_out;

    static int configured = 0;
    const int smem_bytes = 2 * HID * PITCH * sizeof(float);   // 135,168 B
    if (!configured) {
        cudaFuncSetAttribute(eqprop_kernel,
                             cudaFuncAttributeMaxDynamicSharedMemorySize,
                             smem_bytes);
        configured = 1;
    }

    xw1_kernel<<<XCTAS, 256>>>(x, W1);
    eqprop_kernel<<<G, T, smem_bytes>>>(W2, b_h, b_out, h0, o0, n_it, eps, out);
}

// round 16
// speedup vs baseline: 1.2082x; 1.2082x over previous
#include <cuda_runtime.h>
#include <math.h>

// Equilibrium propagation, 256 serial iterations (R15: G=64 pipeline +
// helper-warpgroup split gather).
//
//  - 64 persistent CTAs x 384 threads; CTA c owns 64 output columns.
//  - Pipeline (publish(it+1) depends only on gather(it-1)):
//      Phase A: h-threads (0..127)    gather LOW  32 CTAs' tagged words
//               helpers  (256..383)   gather HIGH 32 CTAs' words -> s_g2
//               o-threads (128..191)  pass1(it) + o Adam
//      Phase B: threads <256 pass2(it+1) split (32 MACs each) ->
//               h publishes tagged partial(it+1) -> hAdam(it) using
//               S = S_low + s_g2[row].
//  - Tagged 8B words {it, f32} via st/ld.relaxed.gpu (single-copy atomic,
//    self-validating). 4-deep buffers (it & 3): publish of it+1 overwrites
//    it-3; gathers of it-3 provably complete first (publish(it+1) requires
//    BOTH gather halves of it done -- enforced by the phase-A barrier).
//  - Each half-sweep is 32 independent loads (single MLP wave, ~260 cyc L2
//    latency); a stale tag re-sweeps only that half.
//  - Redundant h Adam in every CTA (fixed-order sums -> bitwise identical).

#define G      64
#define T      384
#define HID    128
#define OUT    4096
#define COLS   64             // OUT / G
#define HALF_G 32
#define IN     65536
#define XCTAS  256
#define XROWS  (IN / XCTAS)   // 256
#define PITCH_C 132           // col pitch (128 rows + pad)
#define PITCH_R 68            // row pitch (64 cols + pad)

__device__ float g_xpart[XCTAS * HID];
__device__ unsigned long long g_part[4][G][HID];   // [it&3][cta][row] {tag,val}

__device__ __forceinline__ unsigned long long ldx(const unsigned long long* p) {
    unsigned long long v;
    asm volatile("ld.relaxed.gpu.global.b64 %0, [%1];" : "=l"(v) : "l"(p));
    return v;
}
__device__ __forceinline__ void stx(unsigned long long* p, unsigned long long v) {
    asm volatile("st.relaxed.gpu.global.b64 [%0], %1;" :: "l"(p), "l"(v) : "memory");
}
__device__ __forceinline__ float clampf(float v) {
    return fminf(fmaxf(v, 0.f), 1.f);
}
__device__ __forceinline__ unsigned long long pack(int tag, float v) {
    return ((unsigned long long)(unsigned)tag << 32) |
           (unsigned long long)__float_as_uint(v);
}

// Sweep HALF_G tagged words for row `row`, CTAs [k0, k0+32). Blocks until all
// tags match `it`; returns the fixed-order sum of the 32 values.
__device__ __forceinline__ float gather_half(
    const unsigned long long* gb, int k0, int it)
{
    const unsigned long long* b = gb + k0 * HID;
    for (;;) {
        bool ok = true;
        float a0 = 0.f, a1 = 0.f, a2 = 0.f, a3 = 0.f;
#pragma unroll
        for (int k = 0; k < HALF_G; k += 4) {
            unsigned long long v0 = ldx(b + (k + 0) * HID);
            unsigned long long v1 = ldx(b + (k + 1) * HID);
            unsigned long long v2 = ldx(b + (k + 2) * HID);
            unsigned long long v3 = ldx(b + (k + 3) * HID);
            ok &= ((int)(v0 >> 32) == it) & ((int)(v1 >> 32) == it) &
                  ((int)(v2 >> 32) == it) & ((int)(v3 >> 32) == it);
            a0 += __uint_as_float((unsigned)v0);
            a1 += __uint_as_float((unsigned)v1);
            a2 += __uint_as_float((unsigned)v2);
            a3 += __uint_as_float((unsigned)v3);
        }
        if (ok) return (a0 + a1) + (a2 + a3);
    }
}

// ---------------------------------------------------------------------------
// Kernel A: xW1 partials (one-time, HBM-bound) + tag reset of all 4 depths
// (replay safety: stale tags from a prior graph replay must not match).
// ---------------------------------------------------------------------------
__global__ __launch_bounds__(256) void xw1_kernel(
    const float* __restrict__ x, const float* __restrict__ W1)
{
    __shared__ float tmp[HID];
    int t   = threadIdx.x;
    int col = t & (HID - 1);
    int rp  = t >> 7;
    int base = blockIdx.x * XROWS + rp * (XROWS / 2);

    float acc = 0.f;
#pragma unroll 4
    for (int k = 0; k < XROWS / 2; ++k) {
        int i = base + k;
        acc += clampf(x[i]) * W1[(size_t)i * HID + col];
    }
    if (rp == 1) tmp[col] = acc;
    __syncthreads();
    if (rp == 0) g_xpart[blockIdx.x * HID + col] = acc + tmp[col];

    int gid = blockIdx.x * 256 + t;            // 65536 threads; 32768 words
    if (gid < 4 * G * HID)
        ((unsigned long long*)g_part)[gid] = 0ull;
}

// ---------------------------------------------------------------------------
// Kernel B: persistent pipelined iteration kernel.
// ---------------------------------------------------------------------------
extern __shared__ float smem_dyn[];

__global__ __launch_bounds__(T, 1) void eqprop_kernel(
    const float* __restrict__ W2,
    const float* __restrict__ b_h,
    const float* __restrict__ b_out,
    const float* __restrict__ h0,
    const float* __restrict__ o0,
    const int*   __restrict__ n_it_p,
    const float* __restrict__ eps_p,
    float*       __restrict__ out)
{
    float* W2c = smem_dyn;                        // [COLS][PITCH_C] col-major
    float* W2r = smem_dyn + COLS * PITCH_C;       // [HID][PITCH_R]  row-major
    __shared__ __align__(16) float s_rh[HID];     // r_h(it-1) for pass1(it)
    __shared__ __align__(16) float s_ro[COLS];    // r_o(it)   for pass2(it+1)
    __shared__ __align__(16) float s_p2[HID];     // pass2 upper halves
    __shared__ __align__(16) float s_g2[HID];     // gather high-half sums

    const int t = threadIdx.x;
    const int c = blockIdx.x;

    int n_it = *n_it_p;
    if (!(n_it > 0 && n_it < (1 << 20))) {
        n_it = (int)__int_as_float(n_it);
        if (!(n_it > 0 && n_it < (1 << 20))) n_it = 256;
    }
    const float eps = *eps_p;

    // --- W2 slice -> both smem layouts (one-time, coalesced LDG) ---
    for (int idx = t; idx < HID * COLS; idx += T) {
        int i = idx >> 6;            // hidden row  (0..127)
        int j = idx & (COLS - 1);    // local col   (0..63)
        float w = W2[(size_t)i * OUT + (size_t)c * COLS + j];
        W2c[j * PITCH_C + i] = w;
        W2r[i * PITCH_R + j] = w;
    }

    // --- per-thread state ---
    float hreg = 0.f, mh = 0.f, vh = 0.f, bh = 0.f, hW = 0.f;
    float oreg = 0.f, mo = 0.f, vo = 0.f, bo = 0.f;
    if (t < HID) {
        // fixed-order xW1[t] reduction: identical in every CTA -> identical h
        float s0 = 0.f, s1 = 0.f, s2 = 0.f, s3 = 0.f;
#pragma unroll 8
        for (int k = 0; k < XCTAS; k += 4) {
            s0 += g_xpart[(k    ) * HID + t];
            s1 += g_xpart[(k + 1) * HID + t];
            s2 += g_xpart[(k + 2) * HID + t];
            s3 += g_xpart[(k + 3) * HID + t];
        }
        hW   = (s0 + s1) + (s2 + s3);
        hreg = h0[t];
        bh   = b_h[t];
        s_rh[t] = clampf(hreg);
    } else if (t < HID + COLS) {
        int j = t - HID;
        oreg = o0[c * COLS + j];
        bo   = b_out[c * COLS + j];
        s_ro[j] = clampf(oreg);
    }
    __syncthreads();   // W2 smem + s_rh(0) + s_ro(0) ready

    // --- prologue: publish partial(1) = W2 @ r_o(0), tag = 1 ---
    if (t < 2 * HID) {
        const int r    = t & (HID - 1);
        const int half = t >> 7;
        const float4* wr  = (const float4*)(W2r + r * PITCH_R + half * 32);
        const float4* ro4 = (const float4*)(s_ro + half * 32);
        float4 a = make_float4(0.f, 0.f, 0.f, 0.f);
#pragma unroll
        for (int q = 0; q < 8; ++q) {
            float4 w = wr[q], rr = ro4[q];
            a.x += w.x * rr.x; a.y += w.y * rr.y;
            a.z += w.z * rr.z; a.w += w.w * rr.w;
        }
        float phalf = (a.x + a.y) + (a.z + a.w);
        if (half == 1) s_p2[r] = phalf;
        __syncthreads();
        if (t < HID)
            stx(&g_part[1][c][t], pack(1, phalf + s_p2[t]));
    } else {
        __syncthreads();
    }
    __syncthreads();

    float pw1 = 1.f, pw2 = 1.f;

    for (int it = 1; it <= n_it; ++it) {
        pw1 *= 0.9f;
        pw2 *= 0.999f;
        const float ic1 = 1.f / (1.f - pw1);
        const float ic2 = 1.f / (1.f - pw2);

        float S = 0.f;   // low-half gather result (h-threads)

        // ==== phase A ====
        if (t < HID) {
            // low half: CTAs 0..31
            S = gather_half(&g_part[it & 3][0][t], 0, it);
        } else if (t < HID + COLS) {
            // pass1(it) + o Adam
            const int j = t - HID;
            const float4* wc  = (const float4*)(W2c + j * PITCH_C);
            const float4* rh4 = (const float4*)s_rh;
            float4 a = make_float4(0.f, 0.f, 0.f, 0.f);
#pragma unroll
            for (int q = 0; q < HID / 4; ++q) {
                float4 w = wc[q], rr = rh4[q];
                a.x += w.x * rr.x; a.y += w.y * rr.y;
                a.z += w.z * rr.z; a.w += w.w * rr.w;
            }
            float y = (a.x + a.y) + (a.z + a.w);

            float ro   = clampf(oreg);
            float mask = (oreg >= 0.f && oreg <= 1.f) ? 1.f : 0.f;
            float g    = mask * (ro - bo - y);
            mo = 0.9f  * mo + 0.1f  * g;
            vo = 0.999f * vo + 0.001f * g * g;
            oreg -= eps * (mo * ic1) / (sqrtf(vo * ic2) + 1e-8f);
            s_ro[j] = clampf(oreg);               // r_o(it) for pass2(it+1)
        } else if (t >= 2 * HID) {
            // helper: high half (CTAs 32..63) for row t-256
            const int r = t - 2 * HID;
            s_g2[r] = gather_half(&g_part[it & 3][0][r], HALF_G, it);
        }
        __syncthreads();   // s_ro(it) + s_g2 ready; both gather halves done

        // ==== phase B: pass2(it+1) split -> publish(it+1) -> hAdam(it) ====
        if (t < 2 * HID) {
            const int r    = t & (HID - 1);
            const int half = t >> 7;
            const float4* wr  = (const float4*)(W2r + r * PITCH_R + half * 32);
            const float4* ro4 = (const float4*)(s_ro + half * 32);
            float4 a = make_float4(0.f, 0.f, 0.f, 0.f);
#pragma unroll
            for (int q = 0; q < 8; ++q) {
                float4 w = wr[q], rr = ro4[q];
                a.x += w.x * rr.x; a.y += w.y * rr.y;
                a.z += w.z * rr.z; a.w += w.w * rr.w;
            }
            float phalf = (a.x + a.y) + (a.z + a.w);
            if (half == 1) s_p2[r] = phalf;
            __syncthreads();

            if (t < HID) {
                stx(&g_part[(it + 1) & 3][c][t],
                    pack(it + 1, phalf + s_p2[t]));   // publish early

                // redundant h Adam(it): S_total = low + high halves
                float St   = S + s_g2[t];
                float rh   = clampf(hreg);
                float mask = (hreg >= 0.f && hreg <= 1.f) ? 1.f : 0.f;
                float g    = mask * (rh - bh - hW - St);
                mh = 0.9f  * mh + 0.1f  * g;
                vh = 0.999f * vh + 0.001f * g * g;
                hreg -= eps * (mh * ic1) / (sqrtf(vh * ic2) + 1e-8f);
                s_rh[t] = clampf(hreg);               // r_h(it) for pass1(it+1)
            }
        } else {
            __syncthreads();
        }
        __syncthreads();   // s_rh(it) published to o-side
    }

    if (t >= HID && t < HID + COLS)
        out[c * COLS + (t - HID)] = oreg;
}

// ---------------------------------------------------------------------------
extern "C" void kernel_launch(void* const* d_in, const int* in_sizes, int n_in,
                              void* d_out, int out_size)
{
    const float* x     = (const float*)d_in[0];
    const float* W1    = (const float*)d_in[1];
    const float* W2    = (const float*)d_in[2];
    // d_in[3] = b_in (unused by the reference math)
    const float* b_h   = (const float*)d_in[4];
    const float* b_out = (const float*)d_in[5];
    const float* h0    = (const float*)d_in[6];
    const float* o0    = (const float*)d_in[7];
    const int*   n_it  = (const int*)d_in[8];
    const float* eps   = (const float*)d_in[9];
    float* out = (float*)d_out;

    static int configured = 0;
    const int smem_bytes = (COLS * PITCH_C + HID * PITCH_R) * sizeof(float); // 68,608
    if (!configured) {
        cudaFuncSetAttribute(eqprop_kernel,
                             cudaFuncAttributeMaxDynamicSharedMemorySize,
                             smem_bytes);
        configured = 1;
    }

    xw1_kernel<<<XCTAS, 256>>>(x, W1);
    eqprop_kernel<<<G, T, smem_bytes>>>(W2, b_h, b_out, h0, o0, n_it, eps, out);
}

// round 17
// speedup vs baseline: 1.2246x; 1.0136x over previous
#include <cuda_runtime.h>
#include <math.h>

// Equilibrium propagation, 256 serial iterations (R17).
//
//  - 64 persistent CTAs x 320 threads; CTA c owns 64 output columns.
//  - Roles: h = threads 0..127, o = 128..191, helpers = 192..319 (one per
//    h-row).
//  - Pipeline (publish(it+1) depends only on gather(it)):
//      Phase A: h gathers LOW 32 CTAs' tagged words; helpers gather HIGH 32
//               -> s_g2; o does pass1(it) + o Adam -> s_ro.           [bar]
//      Phase B: helpers compute pass2(it+1) whole-row (64 MACs) and publish
//               tagged partial(it+1); h does S = S_low + s_g2, hAdam(it)
//               -> s_rh.                                              [bar]
//    => 2 barriers/iter; publish runs parallel with hAdam; no split/combine.
//  - Tagged 8B words {it, f32} via st/ld.relaxed.gpu (single-copy atomic,
//    self-validating). 4-deep buffers (it & 3): publish of it+1 overwrites
//    it-3; all gathers(it-3) provably complete first (publish(it+1) is
//    bar-ordered after the CTA's full gather(it); induct down the chain).
//  - Gather retry is PREDICATED + PARALLEL: only stale words reload, all in
//    one independent wave (~1 L2 RT per retry instead of a full resweep).
//  - Redundant h Adam in every CTA (fixed-order sums -> bitwise identical).

#define G      64
#define T      320
#define HID    128
#define OUT    4096
#define COLS   64             // OUT / G
#define HALF_G 32
#define IN     65536
#define XCTAS  256
#define XROWS  (IN / XCTAS)   // 256
#define PITCH_C 132           // col pitch (128 rows + pad)
#define PITCH_R 68            // row pitch (64 cols + pad)

__device__ float g_xpart[XCTAS * HID];
__device__ unsigned long long g_part[4][G][HID];   // [it&3][cta][row] {tag,val}

__device__ __forceinline__ unsigned long long ldx(const unsigned long long* p) {
    unsigned long long v;
    asm volatile("ld.relaxed.gpu.global.b64 %0, [%1];" : "=l"(v) : "l"(p));
    return v;
}
__device__ __forceinline__ void stx(unsigned long long* p, unsigned long long v) {
    asm volatile("st.relaxed.gpu.global.b64 [%0], %1;" :: "l"(p), "l"(v) : "memory");
}
__device__ __forceinline__ float clampf(float v) {
    return fminf(fmaxf(v, 0.f), 1.f);
}
__device__ __forceinline__ unsigned long long pack(int tag, float v) {
    return ((unsigned long long)(unsigned)tag << 32) |
           (unsigned long long)__float_as_uint(v);
}

// Sweep HALF_G tagged words (CTAs [k0, k0+32)) for one h-row. First wave loads
// all 32; retries reload ONLY stale entries, predicated + independent.
__device__ __forceinline__ float gather_half(
    const unsigned long long* gb, int k0, int it)
{
    const unsigned long long* b = gb + k0 * HID;
    unsigned long long v[HALF_G];
#pragma unroll
    for (int k = 0; k < HALF_G; ++k) v[k] = ldx(b + k * HID);
    for (;;) {
        bool allok = true;
#pragma unroll
        for (int k = 0; k < HALF_G; ++k)
            allok &= ((int)(v[k] >> 32) == it);
        if (allok) break;
#pragma unroll
        for (int k = 0; k < HALF_G; ++k)
            if ((int)(v[k] >> 32) != it) v[k] = ldx(b + k * HID);  // predicated
    }
    float a0 = 0.f, a1 = 0.f, a2 = 0.f, a3 = 0.f;
#pragma unroll
    for (int k = 0; k < HALF_G; k += 4) {
        a0 += __uint_as_float((unsigned)v[k]);
        a1 += __uint_as_float((unsigned)v[k + 1]);
        a2 += __uint_as_float((unsigned)v[k + 2]);
        a3 += __uint_as_float((unsigned)v[k + 3]);
    }
    return (a0 + a1) + (a2 + a3);
}

// ---------------------------------------------------------------------------
// Kernel A: xW1 partials (one-time, HBM-bound) + tag reset of all 4 depths
// (replay safety: stale tags from a prior graph replay must not match).
// ---------------------------------------------------------------------------
__global__ __launch_bounds__(256) void xw1_kernel(
    const float* __restrict__ x, const float* __restrict__ W1)
{
    __shared__ float tmp[HID];
    int t   = threadIdx.x;
    int col = t & (HID - 1);
    int rp  = t >> 7;
    int base = blockIdx.x * XROWS + rp * (XROWS / 2);

    float acc = 0.f;
#pragma unroll 4
    for (int k = 0; k < XROWS / 2; ++k) {
        int i = base + k;
        acc += clampf(x[i]) * W1[(size_t)i * HID + col];
    }
    if (rp == 1) tmp[col] = acc;
    __syncthreads();
    if (rp == 0) g_xpart[blockIdx.x * HID + col] = acc + tmp[col];

    int gid = blockIdx.x * 256 + t;            // 65536 threads; 32768 words
    if (gid < 4 * G * HID)
        ((unsigned long long*)g_part)[gid] = 0ull;
}

// ---------------------------------------------------------------------------
// Kernel B: persistent pipelined iteration kernel.
// ---------------------------------------------------------------------------
extern __shared__ float smem_dyn[];

__global__ __launch_bounds__(T, 1) void eqprop_kernel(
    const float* __restrict__ W2,
    const float* __restrict__ b_h,
    const float* __restrict__ b_out,
    const float* __restrict__ h0,
    const float* __restrict__ o0,
    const int*   __restrict__ n_it_p,
    const float* __restrict__ eps_p,
    float*       __restrict__ out)
{
    float* W2c = smem_dyn;                        // [COLS][PITCH_C] col-major
    float* W2r = smem_dyn + COLS * PITCH_C;       // [HID][PITCH_R]  row-major
    __shared__ __align__(16) float s_rh[HID];     // r_h(it-1) for pass1(it)
    __shared__ __align__(16) float s_ro[COLS];    // r_o(it)   for pass2(it+1)
    __shared__ __align__(16) float s_g2[HID];     // gather high-half sums

    const int t = threadIdx.x;
    const int c = blockIdx.x;

    int n_it = *n_it_p;
    if (!(n_it > 0 && n_it < (1 << 20))) {
        n_it = (int)__int_as_float(n_it);
        if (!(n_it > 0 && n_it < (1 << 20))) n_it = 256;
    }
    const float eps = *eps_p;

    // --- W2 slice -> both smem layouts (one-time, coalesced LDG) ---
    for (int idx = t; idx < HID * COLS; idx += T) {
        int i = idx >> 6;            // hidden row  (0..127)
        int j = idx & (COLS - 1);    // local col   (0..63)
        float w = W2[(size_t)i * OUT + (size_t)c * COLS + j];
        W2c[j * PITCH_C + i] = w;
        W2r[i * PITCH_R + j] = w;
    }

    // --- per-thread state ---
    float hreg = 0.f, mh = 0.f, vh = 0.f, bh = 0.f, hW = 0.f;
    float oreg = 0.f, mo = 0.f, vo = 0.f, bo = 0.f;
    if (t < HID) {
        // fixed-order xW1[t] reduction: identical in every CTA -> identical h
        float s0 = 0.f, s1 = 0.f, s2 = 0.f, s3 = 0.f;
#pragma unroll 8
        for (int k = 0; k < XCTAS; k += 4) {
            s0 += g_xpart[(k    ) * HID + t];
            s1 += g_xpart[(k + 1) * HID + t];
            s2 += g_xpart[(k + 2) * HID + t];
            s3 += g_xpart[(k + 3) * HID + t];
        }
        hW   = (s0 + s1) + (s2 + s3);
        hreg = h0[t];
        bh   = b_h[t];
        s_rh[t] = clampf(hreg);
    } else if (t < HID + COLS) {
        int j = t - HID;
        oreg = o0[c * COLS + j];
        bo   = b_out[c * COLS + j];
        s_ro[j] = clampf(oreg);
    }
    __syncthreads();   // W2 smem + s_rh(0) + s_ro(0) ready

    // --- prologue: helpers publish partial(1) = W2 @ r_o(0), tag = 1 ---
    if (t >= HID + COLS) {
        const int r = t - (HID + COLS);           // 0..127
        const float4* wr  = (const float4*)(W2r + r * PITCH_R);
        const float4* ro4 = (const float4*)s_ro;
        float4 a = make_float4(0.f, 0.f, 0.f, 0.f);
#pragma unroll
        for (int q = 0; q < COLS / 4; ++q) {
            float4 w = wr[q], rr = ro4[q];
            a.x += w.x * rr.x; a.y += w.y * rr.y;
            a.z += w.z * rr.z; a.w += w.w * rr.w;
        }
        float p = (a.x + a.y) + (a.z + a.w);
        stx(&g_part[1][c][r], pack(1, p));
    }
    __syncthreads();

    float pw1 = 1.f, pw2 = 1.f;

    for (int it = 1; it <= n_it; ++it) {
        pw1 *= 0.9f;
        pw2 *= 0.999f;
        const float ic1 = 1.f / (1.f - pw1);
        const float ic2 = 1.f / (1.f - pw2);

        float S = 0.f;   // low-half gather (h-threads)

        // ==== phase A ====
        if (t < HID) {
            S = gather_half(&g_part[it & 3][0][t], 0, it);
        } else if (t < HID + COLS) {
            const int j = t - HID;
            const float4* wc  = (const float4*)(W2c + j * PITCH_C);
            const float4* rh4 = (const float4*)s_rh;
            float4 a = make_float4(0.f, 0.f, 0.f, 0.f);
#pragma unroll
            for (int q = 0; q < HID / 4; ++q) {
                float4 w = wc[q], rr = rh4[q];
                a.x += w.x * rr.x; a.y += w.y * rr.y;
                a.z += w.z * rr.z; a.w += w.w * rr.w;
            }
            float y = (a.x + a.y) + (a.z + a.w);

            float ro   = clampf(oreg);
            float mask = (oreg >= 0.f && oreg <= 1.f) ? 1.f : 0.f;
            float g    = mask * (ro - bo - y);
            mo = 0.9f  * mo + 0.1f  * g;
            vo = 0.999f * vo + 0.001f * g * g;
            oreg -= eps * (mo * ic1) / (sqrtf(vo * ic2) + 1e-8f);
            s_ro[j] = clampf(oreg);               // r_o(it) for pass2(it+1)
        } else {
            const int r = t - (HID + COLS);
            s_g2[r] = gather_half(&g_part[it & 3][0][r], HALF_G, it);
        }
        __syncthreads();   // s_ro(it), s_g2 ready; both gather halves done

        // ==== phase B: helpers pass2(it+1)+publish  ||  h: hAdam(it) ====
        if (t >= HID + COLS) {
            const int r = t - (HID + COLS);
            const float4* wr  = (const float4*)(W2r + r * PITCH_R);
            const float4* ro4 = (const float4*)s_ro;
            float4 a = make_float4(0.f, 0.f, 0.f, 0.f);
#pragma unroll
            for (int q = 0; q < COLS / 4; ++q) {
                float4 w = wr[q], rr = ro4[q];
                a.x += w.x * rr.x; a.y += w.y * rr.y;
                a.z += w.z * rr.z; a.w += w.w * rr.w;
            }
            float p = (a.x + a.y) + (a.z + a.w);
            stx(&g_part[(it + 1) & 3][c][r], pack(it + 1, p));
        } else if (t < HID) {
            float St   = S + s_g2[t];
            float rh   = clampf(hreg);
            float mask = (hreg >= 0.f && hreg <= 1.f) ? 1.f : 0.f;
            float g    = mask * (rh - bh - hW - St);
            mh = 0.9f  * mh + 0.1f  * g;
            vh = 0.999f * vh + 0.001f * g * g;
            hreg -= eps * (mh * ic1) / (sqrtf(vh * ic2) + 1e-8f);
            s_rh[t] = clampf(hreg);               // r_h(it) for pass1(it+1)
        }
        __syncthreads();   // s_rh(it) visible; publishes ordered before next gather
    }

    if (t >= HID && t < HID + COLS)
        out[c * COLS + (t - HID)] = oreg;
}

// ---------------------------------------------------------------------------
extern "C" void kernel_launch(void* const* d_in, const int* in_sizes, int n_in,
                              void* d_out, int out_size)
{
    const float* x     = (const float*)d_in[0];
    const float* W1    = (const float*)d_in[1];
    const float* W2    = (const float*)d_in[2];
    // d_in[3] = b_in (unused by the reference math)
    const float* b_h   = (const float*)d_in[4];
    const float* b_out = (const float*)d_in[5];
    const float* h0    = (const float*)d_in[6];
    const float* o0    = (const float*)d_in[7];
    const int*   n_it  = (const int*)d_in[8];
    const float* eps   = (const float*)d_in[9];
    float* out = (float*)d_out;

    static int configured = 0;
    const int smem_bytes = (COLS * PITCH_C + HID * PITCH_R) * sizeof(float); // 68,608
    if (!configured) {
        cudaFuncSetAttribute(eqprop_kernel,
                             cudaFuncAttributeMaxDynamicSharedMemorySize,
                             smem_bytes);
        configured = 1;
    }

    xw1_kernel<<<XCTAS, 256>>>(x, W1);
    eqprop_kernel<<<G, T, smem_bytes>>>(W2, b_h, b_out, h0, o0, n_it, eps, out);
}